// round 2
// baseline (speedup 1.0000x reference)
#include <cuda_runtime.h>
#include <cuda_bf16.h>
#include <math.h>

// Problem constants
#define NN 50000
#define EE 400000
#define GG 64
#define IN_CH 128
#define HID 64
#define NHEAD 4
#define CH256 256   // NHEAD*HID

// ---------------- scratch (static __device__ globals; no allocation) ----------
__device__ float  g_xl[NN * CH256];     // 51.2 MB
__device__ float  g_xr[NN * CH256];     // 51.2 MB
__device__ float  g_h [NN * HID];       // 12.8 MB
__device__ int    g_hist[NN];
__device__ int    g_off [NN + 1];
__device__ int    g_cur [NN];
__device__ int    g_csr_src[EE];
__device__ float4 g_csr_eap[EE];
__device__ float  g_pool[GG * HID];
__device__ float  g_cnt [GG];

// ---------------- zero scratch -------------------------------------------------
__global__ void zero_kernel() {
    int idx = blockIdx.x * blockDim.x + threadIdx.x;
    int stride = gridDim.x * blockDim.x;
    for (int i = idx; i < NN; i += stride) g_hist[i] = 0;
    for (int i = idx; i < GG * HID; i += stride) g_pool[i] = 0.f;
    for (int i = idx; i < GG; i += stride) g_cnt[i] = 0.f;
}

// ---------------- histogram of dst ---------------------------------------------
__global__ void hist_kernel(const int* __restrict__ edge_index) {
    int e = blockIdx.x * blockDim.x + threadIdx.x;
    if (e < EE) atomicAdd(&g_hist[edge_index[EE + e]], 1);
}

// ---------------- single-block exclusive scan (warp-based) ---------------------
__global__ void scan_kernel() {
    __shared__ int warp_sums[32];
    __shared__ int carry_s;
    int t = threadIdx.x, lane = t & 31, wid = t >> 5;
    if (t == 0) carry_s = 0;
    __syncthreads();
    for (int base = 0; base < NN; base += 1024) {
        int i = base + t;
        int v = (i < NN) ? g_hist[i] : 0;
        int x = v;
        #pragma unroll
        for (int o = 1; o < 32; o <<= 1) {
            int y = __shfl_up_sync(0xffffffffu, x, o);
            if (lane >= o) x += y;
        }
        if (lane == 31) warp_sums[wid] = x;
        __syncthreads();
        if (wid == 0) {
            int w = warp_sums[lane];
            int xw = w;
            #pragma unroll
            for (int o = 1; o < 32; o <<= 1) {
                int y = __shfl_up_sync(0xffffffffu, xw, o);
                if (lane >= o) xw += y;
            }
            warp_sums[lane] = xw - w;   // exclusive warp offset
        }
        __syncthreads();
        int incl = x + warp_sums[wid];
        int excl = incl - v;
        int cc = carry_s;
        if (i < NN) { g_off[i] = cc + excl; g_cur[i] = cc + excl; }
        __syncthreads();
        if (t == 1023) carry_s = cc + incl;
        __syncthreads();
    }
    if (threadIdx.x == 0) g_off[NN] = carry_s;
}

// ---------------- scatter edges into CSR + edge-attr projection ---------------
__global__ void scatter_kernel(const int* __restrict__ edge_index,
                               const float* __restrict__ edge_attr,
                               const float* __restrict__ W_et, const float* __restrict__ b_et,
                               const float* __restrict__ W_uw, const float* __restrict__ b_uw,
                               const float* __restrict__ W_ua, const float* __restrict__ b_ua) {
    int e = blockIdx.x * blockDim.x + threadIdx.x;
    if (e >= EE) return;
    int s = edge_index[e];
    int d = edge_index[EE + e];
    int pos = atomicAdd(&g_cur[d], 1);
    g_csr_src[pos] = s;
    float et = edge_attr[2 * e];
    float uw = edge_attr[2 * e + 1];
    float ua = 1.f / (1.f + __expf(-(uw * W_ua[0] + b_ua[0])));
    float4 ep;
    ep.x = et * W_et[0] + b_et[0];
    ep.y = et * W_et[1] + b_et[1];
    ep.z = (uw * W_uw[0] + b_uw[0]) * ua;
    ep.w = (uw * W_uw[1] + b_uw[1]) * ua;
    g_csr_eap[pos] = ep;
}

// ---------------- fused xl/xr GEMM:  [N,K] @ [K,256] (x2) + bias ---------------
// USE_GH=true reads the layer input from the __device__ global g_h (cannot pass
// a __device__ symbol as a host-side kernel argument: host code sees the host
// shadow object, and GB300's ATS makes the GPU silently read host zeros).
template <int K, bool USE_GH>
__global__ __launch_bounds__(256) void gemm_lr_kernel(
        const float* __restrict__ x,
        const float* __restrict__ Wl, const float* __restrict__ bl,
        const float* __restrict__ Wr, const float* __restrict__ br) {
    const int NPB = 8;
    __shared__ float xs[NPB][K];
    int node0 = blockIdx.x * NPB;
    int t = threadIdx.x;  // 0..255, one output column
    const float* __restrict__ src = USE_GH ? (const float*)g_h : x;
    for (int i = t; i < NPB * K; i += 256) {
        int r = i / K, c = i % K;
        int n = node0 + r;
        xs[r][c] = (n < NN) ? src[n * K + c] : 0.f;
    }
    __syncthreads();
    float accl[NPB], accr[NPB];
    #pragma unroll
    for (int i = 0; i < NPB; i++) { accl[i] = 0.f; accr[i] = 0.f; }
    for (int k = 0; k < K; k++) {
        float wl = Wl[k * CH256 + t];
        float wr = Wr[k * CH256 + t];
        #pragma unroll
        for (int i = 0; i < NPB; i++) {
            accl[i] = fmaf(xs[i][k], wl, accl[i]);
            accr[i] = fmaf(xs[i][k], wr, accr[i]);
        }
    }
    float bbl = bl[t], bbr = br[t];
    #pragma unroll
    for (int i = 0; i < NPB; i++) {
        int n = node0 + i;
        if (n < NN) {
            g_xl[n * CH256 + t] = accl[i] + bbl;
            g_xr[n * CH256 + t] = accr[i] + bbr;
        }
    }
}

// ---------------- fused GATv2 edge stage: score + softmax + aggregate ----------
// One block per dst node, 128 threads = 4 heads x 32 lanes (each lane: 2 channels).
// out = relu( mean_h( sum_e xl[src]*exp(score_e) / sum_e exp(score_e) ) + bias )
__global__ __launch_bounds__(128) void edge_kernel(
        const float* __restrict__ att, const float* __restrict__ We,
        const float* __restrict__ bias) {
    int n = blockIdx.x;
    int t = threadIdx.x;
    int h = t >> 5, lane = t & 31;
    int c0 = h * 64 + lane;
    int c1 = c0 + 32;
    // per-thread constant weights
    float we00 = We[0 * CH256 + c0], we10 = We[1 * CH256 + c0],
          we20 = We[2 * CH256 + c0], we30 = We[3 * CH256 + c0];
    float we01 = We[0 * CH256 + c1], we11 = We[1 * CH256 + c1],
          we21 = We[2 * CH256 + c1], we31 = We[3 * CH256 + c1];
    float a0 = att[c0], a1 = att[c1];
    float xr0 = g_xr[n * CH256 + c0], xr1 = g_xr[n * CH256 + c1];

    float acc0 = 0.f, acc1 = 0.f, den = 0.f;
    int e0 = g_off[n], e1 = g_off[n + 1];
    for (int e = e0; e < e1; e++) {
        int s = __ldg(&g_csr_src[e]);
        float4 ep = g_csr_eap[e];
        float xla = g_xl[s * CH256 + c0];
        float xlb = g_xl[s * CH256 + c1];
        float ee0 = fmaf(ep.x, we00, fmaf(ep.y, we10, fmaf(ep.z, we20, ep.w * we30)));
        float ee1 = fmaf(ep.x, we01, fmaf(ep.y, we11, fmaf(ep.z, we21, ep.w * we31)));
        float m0 = xla + xr0 + ee0; m0 = (m0 > 0.f) ? m0 : 0.2f * m0;
        float m1 = xlb + xr1 + ee1; m1 = (m1 > 0.f) ? m1 : 0.2f * m1;
        float p = m0 * a0 + m1 * a1;
        #pragma unroll
        for (int o = 16; o; o >>= 1) p += __shfl_xor_sync(0xffffffffu, p, o);
        float ex = expf(p);          // max-subtraction omitted: mathematically identical
        den += ex;
        acc0 = fmaf(xla, ex, acc0);
        acc1 = fmaf(xlb, ex, acc1);
    }
    float inv = 1.f / (den + 1e-16f);
    __shared__ float sm[NHEAD][64];
    sm[h][lane]      = acc0 * inv;
    sm[h][lane + 32] = acc1 * inv;
    __syncthreads();
    if (t < 64) {
        float v = (sm[0][t] + sm[1][t] + sm[2][t] + sm[3][t]) * 0.25f + bias[t];
        g_h[n * HID + t] = (v > 0.f) ? v : 0.f;
    }
}

// ---------------- graph pooling -------------------------------------------------
__global__ void pool_kernel(const int* __restrict__ batch) {
    int idx = blockIdx.x * blockDim.x + threadIdx.x;
    if (idx >= NN * HID) return;
    int n = idx >> 6, c = idx & 63;
    int g = batch[n];
    atomicAdd(&g_pool[g * HID + c], g_h[idx]);
    if (c == 0) atomicAdd(&g_cnt[g], 1.f);
}

// ---------------- head: fc + relu + two linear outputs -------------------------
__global__ __launch_bounds__(64) void final_kernel(
        const float* __restrict__ W_fc, const float* __restrict__ b_fc,
        const float* __restrict__ W_res, const float* __restrict__ b_res,
        const float* __restrict__ W_time, const float* __restrict__ b_time,
        float* __restrict__ out) {
    int g = blockIdx.x;
    int c = threadIdx.x;  // 0..63
    float inv = 1.f / fmaxf(g_cnt[g], 1.f);
    float acc = b_fc[c];
    for (int k = 0; k < HID; k++)
        acc = fmaf(g_pool[g * HID + k] * inv, W_fc[k * HID + c], acc);
    float gv = (acc > 0.f) ? acc : 0.f;
    float r  = gv * W_res[c];
    float tm = gv * W_time[c];
    #pragma unroll
    for (int o = 16; o; o >>= 1) {
        r  += __shfl_xor_sync(0xffffffffu, r, o);
        tm += __shfl_xor_sync(0xffffffffu, tm, o);
    }
    __shared__ float sr[2], st[2];
    if ((c & 31) == 0) { sr[c >> 5] = r; st[c >> 5] = tm; }
    __syncthreads();
    if (c == 0) {
        out[g * 2 + 0] = sr[0] + sr[1] + b_res[0];
        out[g * 2 + 1] = st[0] + st[1] + b_time[0];
    }
}

// ---------------- launcher -------------------------------------------------------
extern "C" void kernel_launch(void* const* d_in, const int* in_sizes, int n_in,
                              void* d_out, int out_size) {
    // input index maps: dict order / reference-signature order / alphabetical keys
    int I_x, I_ea, I_ei, I_b, I_Wet, I_bet, I_Wuw, I_buw, I_Wua, I_bua;
    int I_Wl0, I_bl0, I_Wr0, I_br0, I_att0, I_We0, I_bias0;
    int I_Wl1, I_bl1, I_Wr1, I_br1, I_att1, I_We1, I_bias1;
    int I_Wfc, I_bfc, I_Wres, I_bres, I_Wtime, I_btime;
    if (in_sizes[0] == 2) {
        // alphabetical key order (ASCII: capitals first, '_' < letters)
        // W_et W_fc W_res W_time W_ua W_uw We0 We1 Wl0 Wl1 Wr0 Wr1 att0 att1
        // b_et b_fc b_res b_time b_ua b_uw batch bias0 bias1 bl0 bl1 br0 br1
        // edge_attr edge_index x
        I_Wet = 0; I_Wfc = 1; I_Wres = 2; I_Wtime = 3; I_Wua = 4; I_Wuw = 5;
        I_We0 = 6; I_We1 = 7; I_Wl0 = 8; I_Wl1 = 9; I_Wr0 = 10; I_Wr1 = 11;
        I_att0 = 12; I_att1 = 13;
        I_bet = 14; I_bfc = 15; I_bres = 16; I_btime = 17; I_bua = 18; I_buw = 19;
        I_b = 20; I_bias0 = 21; I_bias1 = 22;
        I_bl0 = 23; I_bl1 = 24; I_br0 = 25; I_br1 = 26;
        I_ea = 27; I_ei = 28; I_x = 29;
    } else if (in_sizes[2] == 2 * EE) {
        // dict insertion order
        I_x = 0; I_ea = 1; I_ei = 2; I_b = 3;
        I_Wet = 4; I_bet = 5; I_Wuw = 6; I_buw = 7; I_Wua = 8; I_bua = 9;
        I_Wl0 = 10; I_bl0 = 11; I_Wr0 = 12; I_br0 = 13; I_att0 = 14; I_We0 = 15; I_bias0 = 16;
        I_Wl1 = 17; I_bl1 = 18; I_Wr1 = 19; I_br1 = 20; I_att1 = 21; I_We1 = 22; I_bias1 = 23;
        I_Wfc = 24; I_bfc = 25; I_Wres = 26; I_bres = 27; I_Wtime = 28; I_btime = 29;
    } else {
        // reference signature order
        I_x = 0; I_ea = 1;
        I_Wet = 2; I_bet = 3; I_Wuw = 4; I_buw = 5; I_Wua = 6; I_bua = 7;
        I_Wl0 = 8; I_bl0 = 9; I_Wr0 = 10; I_br0 = 11; I_att0 = 12; I_We0 = 13; I_bias0 = 14;
        I_Wl1 = 15; I_bl1 = 16; I_Wr1 = 17; I_br1 = 18; I_att1 = 19; I_We1 = 20; I_bias1 = 21;
        I_Wfc = 22; I_bfc = 23; I_Wres = 24; I_bres = 25; I_Wtime = 26; I_btime = 27;
        I_ei = 28; I_b = 29;
    }

    const float* x        = (const float*)d_in[I_x];
    const float* edge_attr= (const float*)d_in[I_ea];
    const int*   edge_idx = (const int*)  d_in[I_ei];
    const int*   batch    = (const int*)  d_in[I_b];
    const float* W_et = (const float*)d_in[I_Wet], *b_et = (const float*)d_in[I_bet];
    const float* W_uw = (const float*)d_in[I_Wuw], *b_uw = (const float*)d_in[I_buw];
    const float* W_ua = (const float*)d_in[I_Wua], *b_ua = (const float*)d_in[I_bua];
    const float* Wl0 = (const float*)d_in[I_Wl0], *bl0 = (const float*)d_in[I_bl0];
    const float* Wr0 = (const float*)d_in[I_Wr0], *br0 = (const float*)d_in[I_br0];
    const float* att0 = (const float*)d_in[I_att0], *We0 = (const float*)d_in[I_We0];
    const float* bias0 = (const float*)d_in[I_bias0];
    const float* Wl1 = (const float*)d_in[I_Wl1], *bl1 = (const float*)d_in[I_bl1];
    const float* Wr1 = (const float*)d_in[I_Wr1], *br1 = (const float*)d_in[I_br1];
    const float* att1 = (const float*)d_in[I_att1], *We1 = (const float*)d_in[I_We1];
    const float* bias1 = (const float*)d_in[I_bias1];
    const float* W_fc = (const float*)d_in[I_Wfc], *b_fc = (const float*)d_in[I_bfc];
    const float* W_res = (const float*)d_in[I_Wres], *b_res = (const float*)d_in[I_bres];
    const float* W_time = (const float*)d_in[I_Wtime], *b_time = (const float*)d_in[I_btime];
    float* out = (float*)d_out;

    // 0) zero scratch
    zero_kernel<<<128, 256>>>();

    // 1) CSR build (dst-sorted)
    hist_kernel<<<(EE + 255) / 256, 256>>>(edge_idx);
    scan_kernel<<<1, 1024>>>();
    scatter_kernel<<<(EE + 255) / 256, 256>>>(edge_idx, edge_attr,
                                              W_et, b_et, W_uw, b_uw, W_ua, b_ua);

    // 2) layer 0
    gemm_lr_kernel<IN_CH, false><<<(NN + 7) / 8, 256>>>(x, Wl0, bl0, Wr0, br0);
    edge_kernel<<<NN, 128>>>(att0, We0, bias0);

    // 3) layer 1 (input read from g_h inside the kernel)
    gemm_lr_kernel<HID, true><<<(NN + 7) / 8, 256>>>(nullptr, Wl1, bl1, Wr1, br1);
    edge_kernel<<<NN, 128>>>(att1, We1, bias1);

    // 4) pooling + head
    pool_kernel<<<(NN * HID + 255) / 256, 256>>>(batch);
    final_kernel<<<GG, 64>>>(W_fc, b_fc, W_res, b_res, W_time, b_time, out);
}